// round 1
// baseline (speedup 1.0000x reference)
#include <cuda_runtime.h>
#include <cstdint>

// GPUBatchProcessor: per-batch 4x4 homogeneous transform of positions +
// 3x3 rotation + renormalization of normals.
//
// Inputs (metadata order):
//   d_in[0]: batch_vertices  float32 [B, N, 6]   (pos.xyz, nrm.xyz)
//   d_in[1]: batch_indices   int32   [B, M, 3]   (UNUSED by reference output)
//   d_in[2]: batch_transforms float32 [B, 4, 4]
// Output: float32 [B, N, 6]  (new_pos.xyz, new_nrm.xyz)
//
// Pure HBM-streaming kernel: 2 vertices (= 3 float4) per thread, fully
// coalesced 128-bit loads/stores. Transforms are warp-uniform __ldg.

static constexpr int BATCH = 8;
static constexpr int NVERT = 1000000;
static constexpr int PAIRS = NVERT / 2;          // 500000 pairs per batch
static constexpr int F4_PER_BATCH = NVERT * 6 / 4; // 1,500,000 float4 per batch

__device__ __forceinline__ void xform_one(
    float x, float y, float z, float nx, float ny, float nz,
    const float m[16],
    float& px, float& py, float& pz, float& ox, float& oy, float& oz)
{
    // position: T @ [x,y,z,1], then divide by w
    float tx = fmaf(m[0], x, fmaf(m[1], y, fmaf(m[2], z, m[3])));
    float ty = fmaf(m[4], x, fmaf(m[5], y, fmaf(m[6], z, m[7])));
    float tz = fmaf(m[8], x, fmaf(m[9], y, fmaf(m[10], z, m[11])));
    float tw = fmaf(m[12], x, fmaf(m[13], y, fmaf(m[14], z, m[15])));
    float rw = __frcp_rn(tw);
    px = tx * rw; py = ty * rw; pz = tz * rw;

    // normal: R @ n, renormalize with clamp
    float ux = fmaf(m[0], nx, fmaf(m[1], ny, m[2] * nz));
    float uy = fmaf(m[4], nx, fmaf(m[5], ny, m[6] * nz));
    float uz = fmaf(m[8], nx, fmaf(m[9], ny, m[10] * nz));
    float ss = fmaf(ux, ux, fmaf(uy, uy, uz * uz));
    float len = fmaxf(sqrtf(ss), 1e-8f);
    float inv = __frcp_rn(len);
    ox = ux * inv; oy = uy * inv; oz = uz * inv;
}

__global__ void __launch_bounds__(256)
batch_xform_kernel(const float4* __restrict__ verts,
                   const float* __restrict__ transforms,
                   float4* __restrict__ out)
{
    int pair = blockIdx.x * blockDim.x + threadIdx.x;
    if (pair >= PAIRS) return;
    int b = blockIdx.y;

    // 16 warp-uniform matrix coefficients -> L1 broadcast
    const float* T = transforms + b * 16;
    float m[16];
#pragma unroll
    for (int i = 0; i < 16; ++i) m[i] = __ldg(T + i);

    long long base = (long long)b * F4_PER_BATCH + (long long)pair * 3;

    float4 a = verts[base];
    float4 c = verts[base + 1];
    float4 d = verts[base + 2];

    // vertex 0: pos (a.x,a.y,a.z), nrm (a.w,c.x,c.y)
    // vertex 1: pos (c.z,c.w,d.x), nrm (d.y,d.z,d.w)
    float p0x, p0y, p0z, n0x, n0y, n0z;
    float p1x, p1y, p1z, n1x, n1y, n1z;
    xform_one(a.x, a.y, a.z, a.w, c.x, c.y, m, p0x, p0y, p0z, n0x, n0y, n0z);
    xform_one(c.z, c.w, d.x, d.y, d.z, d.w, m, p1x, p1y, p1z, n1x, n1y, n1z);

    float4 o0 = make_float4(p0x, p0y, p0z, n0x);
    float4 o1 = make_float4(n0y, n0z, p1x, p1y);
    float4 o2 = make_float4(p1z, n1x, n1y, n1z);

    out[base]     = o0;
    out[base + 1] = o1;
    out[base + 2] = o2;
}

extern "C" void kernel_launch(void* const* d_in, const int* in_sizes, int n_in,
                              void* d_out, int out_size)
{
    const float4* verts = (const float4*)d_in[0];
    const float* transforms = (const float*)d_in[2];
    float4* out = (float4*)d_out;

    dim3 block(256);
    dim3 grid((PAIRS + 255) / 256, BATCH);
    batch_xform_kernel<<<grid, block>>>(verts, transforms, out);
}